// round 8
// baseline (speedup 1.0000x reference)
#include <cuda_runtime.h>
#include <stdint.h>

#define HH 224
#define WW 224
#define STEPS 32
#define NIMG 24            // 8 * 3
#define NSTRIPS 25
#define RPS 9              // site rows per strip: 25*9 = 225 exactly
#define NROWS (RPS + 1)    // staged pixel rows (incl. top halo)
#define NPLANES 4          // per-strip counts <= 9 -> 4 bit-planes
#define SSTRIDE 228        // smem row stride (floats): 912B = 57*16B, conflict-free
#define NV4 ((NROWS * WW) / 4)   // 560 float4 per strip
#define ROWV4 (WW / 4)           // 56 float4 per row

// Per-image/threshold ECC accumulators + completion counter.
// Zero-initialized at load; the last block resets them each launch, so the
// "all zero at entry" invariant holds across graph replays.
__device__ int g_ecc[NIMG * STEPS];
__device__ unsigned int g_done;

// Exact cumulative indicator mask: bit j set iff v <= t_j, where
// t_j = fl(-2 + fl(j * fl(4/31))) (bit-identical to jnp.linspace(-2,2,32) f32).
// Guess g = (v+2)*7.75 + 1/64 bias: floor(clamp(g)) is k* or k*-1; one compare
// v > t_k fixes it exactly. k==32 (v > t_31, incl. +inf) -> 64-bit shift -> 0.
__device__ __forceinline__ unsigned int mask_of(float v) {
    float g = __fmaf_rn(v, 7.75f, 15.515625f);
    g = fminf(fmaxf(g, 0.0f), 31.0f);
    int k = (int)g;
    float t = __fadd_rn(-2.0f, __fmul_rn((float)k, 4.0f / 31.0f));
    k += (v > t) ? 1 : 0;
    return (unsigned int)(0xFFFFFFFFull << k);
}

__global__ __launch_bounds__(256, 4)
void ecc_fused_kernel(const float* __restrict__ x, float* __restrict__ out) {
    const int lane  = threadIdx.x;          // 0..31
    const int w     = threadIdx.y;          // 0..7
    const int tid   = w * 32 + lane;
    const int strip = blockIdx.x;           // 0..NSTRIPS-1
    const int img   = blockIdx.y;           // 0..23
    const int r0    = strip * RPS;          // site rows [r0, r0+RPS)
    const float INF = __int_as_float(0x7f800000);

    __shared__ float s[NROWS * SSTRIDE];    // 9120 B

    // ---- phase 1: cooperative vectorized stage of pixel rows r0-1 .. r0+RPS-1
    {
        const float4* __restrict__ src =
            (const float4*)(x + img * (HH * WW));
        #pragma unroll
        for (int it = 0; it < (NV4 + 255) / 256; ++it) {
            const int idx = tid + it * 256;
            if (idx < NV4) {
                const int row = idx / ROWV4;
                const int c4  = idx - row * ROWV4;
                const int pr  = r0 - 1 + row;           // pixel row (may be OOB)
                float4 v;
                if ((unsigned)pr < (unsigned)HH) v = __ldg(&src[pr * ROWV4 + c4]);
                else v = make_float4(INF, INF, INF, INF);
                *(float4*)&s[row * SSTRIDE + c4 * 4] = v;
            }
        }
    }
    __syncthreads();

    // Lane L of warp w owns pixel column pc = 31*w + L - 1 (lane 0 = halo dup).
    // Site column for lane L>=1 is pc; cols 0..224 covered exactly once
    // (invalid lanes contribute 0: their pmc/mc/pmd factors are 0).
    const int pc    = 31 * w + lane - 1;
    const bool colv = (unsigned)pc < (unsigned)WW;
    const int sidx  = colv ? pc : 0;

    // ---- batched LDS + masks (independent), then batched shfls ----
    unsigned m[NROWS];
    #pragma unroll
    for (int t = 0; t < NROWS; ++t) {
        const float v = colv ? s[t * SSTRIDE + sidx] : INF;
        m[t] = mask_of(v);
    }
    unsigned sm[NROWS];
    #pragma unroll
    for (int t = 0; t < NROWS; ++t) {
        unsigned y = __shfl_up_sync(0xFFFFFFFFu, m[t], 1);
        sm[t] = (lane == 0) ? 0u : y;
    }

    // ---- pure-ALU body: 9 site rows, no rolling dependence ----
    unsigned P[NPLANES], M[NPLANES];
    #pragma unroll
    for (int k = 0; k < NPLANES; ++k) { P[k] = 0u; M[k] = 0u; }

    #pragma unroll
    for (int r = 0; r < RPS; ++r) {
        const unsigned pmc = sm[r],    pmd = m[r];      // row i-1: left, own
        const unsigned mc  = sm[r + 1], md = m[r + 1];  // row i  : left, own
        const unsigned u     = pmd | mc | md;
        const unsigned plus  = pmc & ~u;                // vertex net +1
        const unsigned minus = pmd & mc & ~md;          // edge-pair net -1

        unsigned cp = plus, cm = minus, tp, tm;
        #pragma unroll
        for (int k = 0; k < NPLANES; ++k) {
            tp = P[k] & cp;  tm = M[k] & cm;
            P[k] ^= cp;      M[k] ^= cm;
            cp = tp;         cm = tm;
        }
    }

    // ---- per-warp 32x32 bit transpose (3 instr/stage) + weighted popc ----
    unsigned keepm[5]; int amt[5];
    {
        const unsigned Ms[5] = {0xFFFF0000u, 0xFF00FF00u, 0xF0F0F0F0u,
                                0xCCCCCCCCu, 0xAAAAAAAAu};
        const int ds[5] = {16, 8, 4, 2, 1};
        #pragma unroll
        for (int sgi = 0; sgi < 5; ++sgi) {
            const bool b = (lane & ds[sgi]) != 0;
            keepm[sgi] = b ? Ms[sgi] : ~Ms[sgi];
            amt[sgi]   = b ? ds[sgi] : 32 - ds[sgi];
        }
    }
    int acc = 0;
    #pragma unroll
    for (int k = 0; k < 2 * NPLANES; ++k) {
        unsigned v = (k < NPLANES) ? P[k] : M[k - NPLANES];
        const int ds[5] = {16, 8, 4, 2, 1};
        #pragma unroll
        for (int sgi = 0; sgi < 5; ++sgi) {
            unsigned y = __shfl_xor_sync(0xFFFFFFFFu, v, ds[sgi]);
            unsigned r = __funnelshift_r(y, y, amt[sgi]);  // rotate covers both arms
            v = (v & keepm[sgi]) | (r & ~keepm[sgi]);      // 1 LOP3
        }
        const int wgt = __popc(v) << (k < NPLANES ? k : k - NPLANES);
        acc += (k < NPLANES) ? wgt : -wgt;
    }
    // lane j now holds this warp's net count for threshold j.

    // ---- block combine (no atomics) + one global atomic per threshold ----
    __shared__ int sh[8][STEPS];
    sh[w][lane] = acc;
    __syncthreads();
    if (w == 0) {
        int ssum = 0;
        #pragma unroll
        for (int ww = 0; ww < 8; ++ww) ssum += sh[ww][lane];
        if (ssum != 0) atomicAdd(&g_ecc[img * STEPS + lane], ssum);
    }

    // ---- fused finalize: last block converts g_ecc -> out and resets state ----
    __shared__ unsigned int done;
    __threadfence();
    __syncthreads();
    if (tid == 0) done = atomicAdd(&g_done, 1u);
    __syncthreads();
    if (done == (unsigned)(NSTRIPS * NIMG) - 1u) {
        __threadfence();
        for (int idx = tid; idx < NIMG * STEPS; idx += 256) {
            int v = atomicExch(&g_ecc[idx], 0);   // read + reset for next replay
            out[idx] = (float)v;
        }
        if (tid == 0) g_done = 0u;
    }
}

extern "C" void kernel_launch(void* const* d_in, const int* in_sizes, int n_in,
                              void* d_out, int out_size) {
    const float* x = (const float*)d_in[0];
    float* out = (float*)d_out;
    (void)in_sizes; (void)n_in; (void)out_size;

    dim3 grid(NSTRIPS, NIMG);
    dim3 block(32, 8);
    ecc_fused_kernel<<<grid, block>>>(x, out);
}